// round 14
// baseline (speedup 1.0000x reference)
#include <cuda_runtime.h>

// Fused: (x + s) -> LayerNorm over W=64 -> 2x2x2 avgpool over (D,H,W) -> exact GELU
// Shapes: x (32,32,16,32,64) f32 ; out (32,32,8,16,32) f32
//
// One warp per TWO adjacent pooled output rows (hp = 2*hpq, 2*hpq+1), i.e.
// input rows h0..h0+3 (contiguous 256 floats per d-slice):
//   4 front-batched LDG.128 (MLP_p1=4): {d0,d1} x {h01,h23}, 2KB/warp total.
//   Lower half-warp owns even h-rows, upper half the odd ones (per-half LN rows).
//   LN stats: 4-round butterfly (offsets 8,4,2,1) inside each half; 8 values
//   reduced concurrently = 32 shuffles for 2 outputs.
//   W-pool lane-local; d-pool register-local; h-pool ONE shfl_xor(16) per output
//   (each lane sends the operand its cross-half partner needs, keeps its own).
//   Balanced epilogue: exact GELU as p*normcdff(p), one per lane per output;
//   stores are two full-warp coalesced 128B lines (64 consecutive floats/warp).

#define LN_EPS 1e-5f

__global__ __launch_bounds__(256, 4)
void fused_ln_pool_gelu_kernel(const float* __restrict__ x,
                               const float* __restrict__ sum_weight,
                               const float* __restrict__ gamma,
                               const float* __restrict__ beta,
                               float* __restrict__ out)
{
    const int lane = threadIdx.x & 31;
    const int lh   = lane & 15;                  // lane within half-warp
    const int half = lane >> 4;                  // 0 = even h-row, 1 = odd h-row
    const int warp = threadIdx.x >> 5;
    const int g    = (blockIdx.x << 3) + warp;   // global warp id, 65536 total

    // g -> (n, c, dp, hpq); each warp covers pooled rows hp = 2*hpq, 2*hpq+1
    const int hpq = g & 7;
    const int dp  = (g >> 3) & 7;
    const int c   = (g >> 6) & 31;
    const int n   = g >> 11;

    const float s = __ldg(sum_weight);

    // input strides (floats): w:1, h:64, d:2048, c:32768, n:1048576
    const size_t base = ((((size_t)n * 32 + c) * 16 + (dp << 1)) * 32 + (hpq << 2)) * 64;

    // Four independent 512B warp loads (front-batched, MLP=4):
    //   A0: d0, rows h0/h0+1   A1: d0, rows h0+2/h0+3
    //   B0: d1, rows h0/h0+1   B1: d1, rows h0+2/h0+3
    float4 va0 = __ldg(reinterpret_cast<const float4*>(x + base)               + lane);
    float4 va1 = __ldg(reinterpret_cast<const float4*>(x + base + 128)         + lane);
    float4 vb0 = __ldg(reinterpret_cast<const float4*>(x + base + 2048)        + lane);
    float4 vb1 = __ldg(reinterpret_cast<const float4*>(x + base + 2048 + 128)  + lane);

    // affine params for this lane's 4 w-positions (4*lh .. 4*lh+3); shared by both outputs
    const float4 gw = __ldg(reinterpret_cast<const float4*>(gamma) + lh);
    const float4 bw = __ldg(reinterpret_cast<const float4*>(beta)  + lh);

    va0.x += s; va0.y += s; va0.z += s; va0.w += s;
    va1.x += s; va1.y += s; va1.z += s; va1.w += s;
    vb0.x += s; vb0.y += s; vb0.z += s; vb0.w += s;
    vb1.x += s; vb1.y += s; vb1.z += s; vb1.w += s;

    // per-lane partial sums / sumsq (each lane: 4 consecutive w of ONE h-row per load)
    float sa0 = (va0.x + va0.y) + (va0.z + va0.w);
    float sa1 = (va1.x + va1.y) + (va1.z + va1.w);
    float sb0 = (vb0.x + vb0.y) + (vb0.z + vb0.w);
    float sb1 = (vb1.x + vb1.y) + (vb1.z + vb1.w);
    float qa0 = fmaf(va0.x, va0.x, fmaf(va0.y, va0.y, fmaf(va0.z, va0.z, va0.w * va0.w)));
    float qa1 = fmaf(va1.x, va1.x, fmaf(va1.y, va1.y, fmaf(va1.z, va1.z, va1.w * va1.w)));
    float qb0 = fmaf(vb0.x, vb0.x, fmaf(vb0.y, vb0.y, fmaf(vb0.z, vb0.z, vb0.w * vb0.w)));
    float qb1 = fmaf(vb1.x, vb1.x, fmaf(vb1.y, vb1.y, fmaf(vb1.z, vb1.z, vb1.w * vb1.w)));

    // per-half butterfly: offsets 8,4,2,1 never cross the half boundary; each
    // 16-lane half reduces its own h-row. 8 values x 4 rounds = 32 shuffles.
    #pragma unroll
    for (int off = 8; off > 0; off >>= 1) {
        sa0 += __shfl_xor_sync(0xFFFFFFFFu, sa0, off);
        sa1 += __shfl_xor_sync(0xFFFFFFFFu, sa1, off);
        sb0 += __shfl_xor_sync(0xFFFFFFFFu, sb0, off);
        sb1 += __shfl_xor_sync(0xFFFFFFFFu, sb1, off);
        qa0 += __shfl_xor_sync(0xFFFFFFFFu, qa0, off);
        qa1 += __shfl_xor_sync(0xFFFFFFFFu, qa1, off);
        qb0 += __shfl_xor_sync(0xFFFFFFFFu, qb0, off);
        qb1 += __shfl_xor_sync(0xFFFFFFFFu, qb1, off);
    }

    const float inv64 = 1.0f / 64.0f;
    const float ma0 = sa0 * inv64, ma1 = sa1 * inv64;
    const float mb0 = sb0 * inv64, mb1 = sb1 * inv64;
    const float ra0 = rsqrtf(fmaf(-ma0, ma0, qa0 * inv64) + LN_EPS);
    const float ra1 = rsqrtf(fmaf(-ma1, ma1, qa1 * inv64) + LN_EPS);
    const float rb0 = rsqrtf(fmaf(-mb0, mb0, qb0 * inv64) + LN_EPS);
    const float rb1 = rsqrtf(fmaf(-mb1, mb1, qb1 * inv64) + LN_EPS);

    // LN + lane-local W-pool pairs + register d-pool, per pipeline.
    // e = pooled-w index 2*lh (w 4lh..4lh+1), o = pooled-w index 2*lh+1 (w 4lh+2..4lh+3)
    // pipeline 0 (output row 2g):   va0 (d0) + vb0 (d1)
    const float p0e = fmaf((va0.x - ma0) * ra0, gw.x, bw.x) + fmaf((va0.y - ma0) * ra0, gw.y, bw.y)
                    + fmaf((vb0.x - mb0) * rb0, gw.x, bw.x) + fmaf((vb0.y - mb0) * rb0, gw.y, bw.y);
    const float p0o = fmaf((va0.z - ma0) * ra0, gw.z, bw.z) + fmaf((va0.w - ma0) * ra0, gw.w, bw.w)
                    + fmaf((vb0.z - mb0) * rb0, gw.z, bw.z) + fmaf((vb0.w - mb0) * rb0, gw.w, bw.w);
    // pipeline 1 (output row 2g+1): va1 (d0) + vb1 (d1)
    const float p1e = fmaf((va1.x - ma1) * ra1, gw.x, bw.x) + fmaf((va1.y - ma1) * ra1, gw.y, bw.y)
                    + fmaf((vb1.x - mb1) * rb1, gw.x, bw.x) + fmaf((vb1.y - mb1) * rb1, gw.y, bw.y);
    const float p1o = fmaf((va1.z - ma1) * ra1, gw.z, bw.z) + fmaf((va1.w - ma1) * ra1, gw.w, bw.w)
                    + fmaf((vb1.z - mb1) * rb1, gw.z, bw.z) + fmaf((vb1.w - mb1) * rb1, gw.w, bw.w);

    // h-pool with ONE exchange per output: each lane keeps the operand it will
    // output (lower half: e, upper half: o) and sends the one its partner needs.
    const float keep0 = half ? p0o : p0e;
    const float send0 = half ? p0e : p0o;
    const float keep1 = half ? p1o : p1e;
    const float send1 = half ? p1e : p1o;
    const float u0 = (keep0 + __shfl_xor_sync(0xFFFFFFFFu, send0, 16)) * 0.125f;
    const float u1 = (keep1 + __shfl_xor_sync(0xFFFFFFFFu, send1, 16)) * 0.125f;

    // Exact GELU via the normal CDF: gelu(p) = p * Phi(p). One per lane per output.
    const float y0 = u0 * normcdff(u0);
    const float y1 = u1 * normcdff(u1);

    // Output base for pooled row 2g: g*64 floats; lower half writes even pooled-w,
    // upper half odd -> full-warp permutation of one 128B line per output row.
    float* ob = out + (size_t)g * 64;
    ob[(lh << 1) + half]      = y0;              // output row 2g
    ob[32 + (lh << 1) + half] = y1;              // output row 2g+1
}

extern "C" void kernel_launch(void* const* d_in, const int* in_sizes, int n_in,
                              void* d_out, int out_size)
{
    const float* x          = (const float*)d_in[0];
    const float* sum_weight = (const float*)d_in[1];
    const float* gamma      = (const float*)d_in[2];
    const float* beta       = (const float*)d_in[3];
    float* out              = (float*)d_out;

    // 65536 warps (2 pooled rows each) -> 8192 blocks of 256 threads
    fused_ln_pool_gelu_kernel<<<8192, 256>>>(x, sum_weight, gamma, beta, out);
}

// round 15
// speedup vs baseline: 1.1303x; 1.1303x over previous
#include <cuda_runtime.h>

// Fused: (x + s) -> LayerNorm over W=64 -> 2x2x2 avgpool over (D,H,W) -> exact GELU
// Shapes: x (32,32,16,32,64) f32 ; out (32,32,8,16,32) f32
//
// KEY ALGEBRA: LayerNorm is shift-invariant, so the scalar add of sum_weight
// cancels exactly ((x+s) - mean(x+s) = x - mean(x); var unchanged). The kernel
// therefore never reads sum_weight and does zero per-element adds for it.
//
// One warp per TWO adjacent pooled output rows (hp = 2*hpq, 2*hpq+1), i.e.
// input rows h0..h0+3 (contiguous 256 floats per d-slice):
//   4 front-batched LDG.128 (MLP_p1=4): {d0,d1} x {h01,h23}, 2KB/warp total.
//   Lower half-warp owns even h-rows, upper half the odd ones (per-half LN rows).
//   LN stats: 4-round butterfly (offsets 8,4,2,1) inside each half; 8 values
//   reduced concurrently = 32 shuffles for 2 outputs.
//   W-pool lane-local; d-pool register-local; h-pool ONE shfl_xor(16) per output.
//   Balanced epilogue: exact GELU via erff (fast path), one per lane per output;
//   stores are two full-warp coalesced 128B lines (64 consecutive floats/warp).

#define LN_EPS       1e-5f
#define INV_SQRT2_F  0.7071067811865476f

__global__ __launch_bounds__(256, 6)
void fused_ln_pool_gelu_kernel(const float* __restrict__ x,
                               const float* __restrict__ gamma,
                               const float* __restrict__ beta,
                               float* __restrict__ out)
{
    const int lane = threadIdx.x & 31;
    const int lh   = lane & 15;                  // lane within half-warp
    const int half = lane >> 4;                  // 0 = even h-row, 1 = odd h-row
    const int warp = threadIdx.x >> 5;
    const int g    = (blockIdx.x << 3) + warp;   // global warp id, 65536 total

    // g -> (n, c, dp, hpq); each warp covers pooled rows hp = 2*hpq, 2*hpq+1
    const int hpq = g & 7;
    const int dp  = (g >> 3) & 7;
    const int c   = (g >> 6) & 31;
    const int n   = g >> 11;

    // input strides (floats): w:1, h:64, d:2048, c:32768, n:1048576
    const size_t base = ((((size_t)n * 32 + c) * 16 + (dp << 1)) * 32 + (hpq << 2)) * 64;

    // Four independent 512B warp loads (front-batched, MLP=4):
    //   A0: d0, rows h0/h0+1   A1: d0, rows h0+2/h0+3
    //   B0: d1, rows h0/h0+1   B1: d1, rows h0+2/h0+3
    float4 va0 = __ldg(reinterpret_cast<const float4*>(x + base)               + lane);
    float4 va1 = __ldg(reinterpret_cast<const float4*>(x + base + 128)         + lane);
    float4 vb0 = __ldg(reinterpret_cast<const float4*>(x + base + 2048)        + lane);
    float4 vb1 = __ldg(reinterpret_cast<const float4*>(x + base + 2048 + 128)  + lane);

    // affine params for this lane's 4 w-positions (4*lh .. 4*lh+3); shared by both outputs
    const float4 gw = __ldg(reinterpret_cast<const float4*>(gamma) + lh);
    const float4 bw = __ldg(reinterpret_cast<const float4*>(beta)  + lh);

    // per-lane partial sums / sumsq on raw x (sum_weight cancels through LN)
    float sa0 = (va0.x + va0.y) + (va0.z + va0.w);
    float sa1 = (va1.x + va1.y) + (va1.z + va1.w);
    float sb0 = (vb0.x + vb0.y) + (vb0.z + vb0.w);
    float sb1 = (vb1.x + vb1.y) + (vb1.z + vb1.w);
    float qa0 = fmaf(va0.x, va0.x, fmaf(va0.y, va0.y, fmaf(va0.z, va0.z, va0.w * va0.w)));
    float qa1 = fmaf(va1.x, va1.x, fmaf(va1.y, va1.y, fmaf(va1.z, va1.z, va1.w * va1.w)));
    float qb0 = fmaf(vb0.x, vb0.x, fmaf(vb0.y, vb0.y, fmaf(vb0.z, vb0.z, vb0.w * vb0.w)));
    float qb1 = fmaf(vb1.x, vb1.x, fmaf(vb1.y, vb1.y, fmaf(vb1.z, vb1.z, vb1.w * vb1.w)));

    // per-half butterfly: offsets 8,4,2,1 never cross the half boundary; each
    // 16-lane half reduces its own h-row. 8 values x 4 rounds = 32 shuffles.
    #pragma unroll
    for (int off = 8; off > 0; off >>= 1) {
        sa0 += __shfl_xor_sync(0xFFFFFFFFu, sa0, off);
        sa1 += __shfl_xor_sync(0xFFFFFFFFu, sa1, off);
        sb0 += __shfl_xor_sync(0xFFFFFFFFu, sb0, off);
        sb1 += __shfl_xor_sync(0xFFFFFFFFu, sb1, off);
        qa0 += __shfl_xor_sync(0xFFFFFFFFu, qa0, off);
        qa1 += __shfl_xor_sync(0xFFFFFFFFu, qa1, off);
        qb0 += __shfl_xor_sync(0xFFFFFFFFu, qb0, off);
        qb1 += __shfl_xor_sync(0xFFFFFFFFu, qb1, off);
    }

    const float inv64 = 1.0f / 64.0f;
    const float ma0 = sa0 * inv64, ma1 = sa1 * inv64;
    const float mb0 = sb0 * inv64, mb1 = sb1 * inv64;
    const float ra0 = rsqrtf(fmaf(-ma0, ma0, qa0 * inv64) + LN_EPS);
    const float ra1 = rsqrtf(fmaf(-ma1, ma1, qa1 * inv64) + LN_EPS);
    const float rb0 = rsqrtf(fmaf(-mb0, mb0, qb0 * inv64) + LN_EPS);
    const float rb1 = rsqrtf(fmaf(-mb1, mb1, qb1 * inv64) + LN_EPS);

    // LN + lane-local W-pool pairs + register d-pool, per pipeline.
    // e = pooled-w index 2*lh (w 4lh..4lh+1), o = pooled-w index 2*lh+1 (w 4lh+2..4lh+3)
    // pipeline 0 (output row 2g):   va0 (d0) + vb0 (d1)
    const float p0e = fmaf((va0.x - ma0) * ra0, gw.x, bw.x) + fmaf((va0.y - ma0) * ra0, gw.y, bw.y)
                    + fmaf((vb0.x - mb0) * rb0, gw.x, bw.x) + fmaf((vb0.y - mb0) * rb0, gw.y, bw.y);
    const float p0o = fmaf((va0.z - ma0) * ra0, gw.z, bw.z) + fmaf((va0.w - ma0) * ra0, gw.w, bw.w)
                    + fmaf((vb0.z - mb0) * rb0, gw.z, bw.z) + fmaf((vb0.w - mb0) * rb0, gw.w, bw.w);
    // pipeline 1 (output row 2g+1): va1 (d0) + vb1 (d1)
    const float p1e = fmaf((va1.x - ma1) * ra1, gw.x, bw.x) + fmaf((va1.y - ma1) * ra1, gw.y, bw.y)
                    + fmaf((vb1.x - mb1) * rb1, gw.x, bw.x) + fmaf((vb1.y - mb1) * rb1, gw.y, bw.y);
    const float p1o = fmaf((va1.z - ma1) * ra1, gw.z, bw.z) + fmaf((va1.w - ma1) * ra1, gw.w, bw.w)
                    + fmaf((vb1.z - mb1) * rb1, gw.z, bw.z) + fmaf((vb1.w - mb1) * rb1, gw.w, bw.w);

    // h-pool with ONE exchange per output: each lane keeps the operand it will
    // output (lower half: e, upper half: o) and sends the one its partner needs.
    const float keep0 = half ? p0o : p0e;
    const float send0 = half ? p0e : p0o;
    const float keep1 = half ? p1o : p1e;
    const float send1 = half ? p1e : p1o;
    const float u0 = (keep0 + __shfl_xor_sync(0xFFFFFFFFu, send0, 16)) * 0.125f;
    const float u1 = (keep1 + __shfl_xor_sync(0xFFFFFFFFu, send1, 16)) * 0.125f;

    // Exact GELU via erff (fast polynomial path; normcdff was ~2-3x more instrs).
    const float y0 = 0.5f * u0 * (1.0f + erff(u0 * INV_SQRT2_F));
    const float y1 = 0.5f * u1 * (1.0f + erff(u1 * INV_SQRT2_F));

    // Output base for pooled row 2g: g*64 floats; lower half writes even pooled-w,
    // upper half odd -> full-warp permutation of one 128B line per output row.
    float* ob = out + (size_t)g * 64;
    ob[(lh << 1) + half]      = y0;              // output row 2g
    ob[32 + (lh << 1) + half] = y1;              // output row 2g+1
}

extern "C" void kernel_launch(void* const* d_in, const int* in_sizes, int n_in,
                              void* d_out, int out_size)
{
    const float* x     = (const float*)d_in[0];
    // d_in[1] = sum_weight: unused — LayerNorm is shift-invariant, the scalar
    // add cancels exactly in (v - mean) and in the variance.
    const float* gamma = (const float*)d_in[2];
    const float* beta  = (const float*)d_in[3];
    float* out         = (float*)d_out;

    // 65536 warps (2 pooled rows each) -> 8192 blocks of 256 threads
    fused_ln_pool_gelu_kernel<<<8192, 256>>>(x, gamma, beta, out);
}